// round 8
// baseline (speedup 1.0000x reference)
#include <cuda_runtime.h>
#include <math.h>
#include <stdint.h>

// Problem constants
#define S_LEN 2048
#define BATCH 2
#define HID   2048
#define NHEAD 16
#define HDIM  128
#define NH_B  (BATCH * NHEAD)   // 32 heads total

// Scratch (device globals: no allocation allowed in kernel_launch)
__device__ float g_q[(size_t)NH_B * S_LEN * HDIM];     // [b*NH+nh][s][hd]
__device__ float g_k[(size_t)NH_B * S_LEN * HDIM];
__device__ float g_v[(size_t)NH_B * S_LEN * HDIM];
__device__ float g_attn[(size_t)S_LEN * BATCH * HID];  // [s][b][h]
__device__ float g_tab[S_LEN * 64 * 2];                // cos/sin table

// ---------------------------------------------------------------------------
// Helpers: tf32 conversion + hi/lo split + m16n8k8 mma
// ---------------------------------------------------------------------------
__device__ __forceinline__ uint32_t f2tf(float x) {
    uint32_t r;
    asm("cvt.rna.tf32.f32 %0, %1;" : "=r"(r) : "f"(x));
    return r;
}

__device__ __forceinline__ void split2(float x, float& hi, float& lo) {
    uint32_t h = f2tf(x);
    hi = __uint_as_float(h);
    lo = __uint_as_float(f2tf(x - hi));
}

__device__ __forceinline__ void mma8(float c[4], const uint32_t a[4],
                                     uint32_t b0, uint32_t b1) {
    asm volatile(
        "mma.sync.aligned.m16n8k8.row.col.f32.tf32.tf32.f32 "
        "{%0,%1,%2,%3}, {%4,%5,%6,%7}, {%8,%9}, {%0,%1,%2,%3};"
        : "+f"(c[0]), "+f"(c[1]), "+f"(c[2]), "+f"(c[3])
        : "r"(a[0]), "r"(a[1]), "r"(a[2]), "r"(a[3]), "r"(b0), "r"(b1));
}

// ---------------------------------------------------------------------------
// GEMM: C[M,N] = A[M,K] * W[N,K]^T  (tf32x2, fp32-accurate)
// MODE 0: A = hidden_states, epilogue scatters into g_q/g_k/g_v ([b,nh,s,hd])
// MODE 1: A = g_attn, epilogue writes C[row*N+col] (final output)
// Block 128x128x32, 256 threads (8 warps as 4x2, warp tile 32x64).
// ---------------------------------------------------------------------------
#define GBM 128
#define GBN 128
#define GBK 32
#define GLDA 36   // 32 + pad 4 (keeps 16B alignment, conflict-free frag reads)

template<int MODE>
__global__ void __launch_bounds__(256, 2)
gemm_kernel(const float* __restrict__ A, const float* __restrict__ W,
            float* __restrict__ C, int M, int N, int K)
{
    extern __shared__ float sm[];
    float* Ah = sm;
    float* Al = Ah + GBM * GLDA;
    float* Bh = Al + GBM * GLDA;
    float* Bl = Bh + GBM * GLDA;

    const float* Ap = (MODE == 1) ? g_attn : A;

    const int t = threadIdx.x;
    const int warp = t >> 5, lane = t & 31;
    const int bm = blockIdx.y * GBM;
    const int bn = blockIdx.x * GBN;
    const int wm = (warp >> 1) * 32;
    const int wn = (warp & 1) * 64;
    const int lr = t >> 3;          // 0..31
    const int lc = (t & 7) * 4;     // 0,4,...,28
    const int qr = lane >> 2;       // 0..7
    const int qc = lane & 3;        // 0..3

    float acc[2][8][4];
    #pragma unroll
    for (int i = 0; i < 2; i++)
        #pragma unroll
        for (int j = 0; j < 8; j++)
            #pragma unroll
            for (int e = 0; e < 4; e++) acc[i][j][e] = 0.f;

    for (int kt = 0; kt < K; kt += GBK) {
        __syncthreads();
        #pragma unroll
        for (int i = 0; i < 4; i++) {
            int row = lr + i * 32;
            float4 va = *(const float4*)(Ap + (size_t)(bm + row) * K + kt + lc);
            float4 vb = *(const float4*)(W  + (size_t)(bn + row) * K + kt + lc);
            float h, l;
            float* ah = Ah + row * GLDA + lc; float* al = Al + row * GLDA + lc;
            split2(va.x, h, l); ah[0] = h; al[0] = l;
            split2(va.y, h, l); ah[1] = h; al[1] = l;
            split2(va.z, h, l); ah[2] = h; al[2] = l;
            split2(va.w, h, l); ah[3] = h; al[3] = l;
            float* bh = Bh + row * GLDA + lc; float* bl = Bl + row * GLDA + lc;
            split2(vb.x, h, l); bh[0] = h; bl[0] = l;
            split2(vb.y, h, l); bh[1] = h; bl[1] = l;
            split2(vb.z, h, l); bh[2] = h; bl[2] = l;
            split2(vb.w, h, l); bh[3] = h; bl[3] = l;
        }
        __syncthreads();

        #pragma unroll
        for (int ks = 0; ks < 4; ks++) {
            const int k0 = ks * 8 + qc;
            uint32_t fah[2][4], fal[2][4];
            #pragma unroll
            for (int mi = 0; mi < 2; mi++) {
                int r = wm + mi * 16 + qr;
                fah[mi][0] = __float_as_uint(Ah[r * GLDA + k0]);
                fah[mi][1] = __float_as_uint(Ah[(r + 8) * GLDA + k0]);
                fah[mi][2] = __float_as_uint(Ah[r * GLDA + k0 + 4]);
                fah[mi][3] = __float_as_uint(Ah[(r + 8) * GLDA + k0 + 4]);
                fal[mi][0] = __float_as_uint(Al[r * GLDA + k0]);
                fal[mi][1] = __float_as_uint(Al[(r + 8) * GLDA + k0]);
                fal[mi][2] = __float_as_uint(Al[r * GLDA + k0 + 4]);
                fal[mi][3] = __float_as_uint(Al[(r + 8) * GLDA + k0 + 4]);
            }
            #pragma unroll
            for (int ni = 0; ni < 8; ni++) {
                int cb = wn + ni * 8 + qr;
                uint32_t bh0 = __float_as_uint(Bh[cb * GLDA + k0]);
                uint32_t bh1 = __float_as_uint(Bh[cb * GLDA + k0 + 4]);
                uint32_t bl0 = __float_as_uint(Bl[cb * GLDA + k0]);
                uint32_t bl1 = __float_as_uint(Bl[cb * GLDA + k0 + 4]);
                #pragma unroll
                for (int mi = 0; mi < 2; mi++) {
                    mma8(acc[mi][ni], fah[mi], bh0, bh1);
                    mma8(acc[mi][ni], fah[mi], bl0, bl1);
                    mma8(acc[mi][ni], fal[mi], bh0, bh1);
                }
            }
        }
    }

    // Epilogue
    #pragma unroll
    for (int mi = 0; mi < 2; mi++)
        #pragma unroll
        for (int ni = 0; ni < 8; ni++)
            #pragma unroll
            for (int e = 0; e < 4; e++) {
                int row = bm + wm + mi * 16 + qr + ((e >> 1) << 3);
                int col = bn + wn + ni * 8 + 2 * qc + (e & 1);
                float v = acc[mi][ni][e];
                if (MODE == 0) {
                    int tsel = col >> 11;          // 0=q 1=k 2=v
                    int rem  = col & 2047;
                    int nh = rem >> 7, hd = rem & 127;
                    int s = row >> 1, b = row & 1;
                    float* dst = (tsel == 0) ? g_q : ((tsel == 1) ? g_k : g_v);
                    dst[((size_t)(b * NHEAD + nh) * S_LEN + s) * HDIM + hd] = v;
                } else {
                    C[(size_t)row * N + col] = v;
                }
            }
}

// ---------------------------------------------------------------------------
// RoPE cos/sin table (mimics fp32 theta rounding of reference), then apply.
// ---------------------------------------------------------------------------
__global__ void rope_table_kernel()
{
    int idx = blockIdx.x * blockDim.x + threadIdx.x;   // 2048*64
    int s = idx >> 6, d = idx & 63;
    float e = (float)d * (1.0f / 64.0f);
    float inv = 1.0f / powf(10000.0f, e);
    float th = (float)s * inv;                          // fp32 theta like ref
    double sd, cd;
    sincos((double)th, &sd, &cd);
    g_tab[idx * 2 + 0] = (float)cd;
    g_tab[idx * 2 + 1] = (float)sd;
}

__global__ void rope_apply_kernel()
{
    int i = blockIdx.x * blockDim.x + threadIdx.x;  // 2 * 32 * 2048 * 64
    int d = i & 63;
    int s = (i >> 6) & 2047;
    int h = (i >> 17) & 31;
    int w = i >> 22;
    float c  = g_tab[((s << 6) + d) * 2 + 0];
    float sn = g_tab[((s << 6) + d) * 2 + 1];
    float* buf = w ? g_k : g_q;
    size_t base = ((size_t)h * S_LEN + s) * HDIM;
    float x0 = buf[base + d];
    float x1 = buf[base + d + 64];
    buf[base + d]      = x0 * c - x1 * sn;
    buf[base + d + 64] = x1 * c + x0 * sn;
}

// ---------------------------------------------------------------------------
// Causal flash attention: 64 q-rows per CTA, 4 warps (16 rows each),
// tf32x2 for Q/K and P, single tf32 (rna) for V. fp32 softmax stats.
// ---------------------------------------------------------------------------
#define ALD 132   // 128 + pad 4
#define PLD 68    // 64 + pad 4

__global__ void __launch_bounds__(128, 1)
attn_kernel()
{
    extern __shared__ float sm[];
    float* Qh = sm;
    float* Ql = Qh + 64 * ALD;
    float* Kh = Ql + 64 * ALD;
    float* Kl = Kh + 64 * ALD;
    float* Vs = Kl + 64 * ALD;
    float* Ph = Vs + 64 * ALD;
    float* Pl = Ph + 64 * PLD;

    const int t = threadIdx.x, warp = t >> 5, lane = t & 31;
    const int qr = lane >> 2, qc = lane & 3;
    const int qb = blockIdx.x, hb = blockIdx.y;
    const size_t head_off = (size_t)hb * S_LEN * HDIM;
    const int wrow = warp * 16;

    // Load + split Q tile (64 x 128)
    {
        const float* qp = g_q + head_off + (size_t)qb * 64 * HDIM;
        for (int i = t * 4; i < 64 * 128; i += 128 * 4) {
            int r = i >> 7, c = i & 127;
            float4 v = *(const float4*)(qp + r * 128 + c);
            float h, l;
            split2(v.x, h, l); Qh[r * ALD + c + 0] = h; Ql[r * ALD + c + 0] = l;
            split2(v.y, h, l); Qh[r * ALD + c + 1] = h; Ql[r * ALD + c + 1] = l;
            split2(v.z, h, l); Qh[r * ALD + c + 2] = h; Ql[r * ALD + c + 2] = l;
            split2(v.w, h, l); Qh[r * ALD + c + 3] = h; Ql[r * ALD + c + 3] = l;
        }
    }

    float oacc[16][4];
    #pragma unroll
    for (int i = 0; i < 16; i++)
        #pragma unroll
        for (int e = 0; e < 4; e++) oacc[i][e] = 0.f;
    float m0 = -INFINITY, m1 = -INFINITY, l0 = 0.f, l1 = 0.f;

    for (int j = 0; j <= qb; j++) {
        __syncthreads();
        {
            const float* kp = g_k + head_off + (size_t)j * 64 * HDIM;
            const float* vp = g_v + head_off + (size_t)j * 64 * HDIM;
            for (int i = t * 4; i < 64 * 128; i += 128 * 4) {
                int r = i >> 7, c = i & 127;
                float4 kv = *(const float4*)(kp + r * 128 + c);
                float h, l;
                split2(kv.x, h, l); Kh[r * ALD + c + 0] = h; Kl[r * ALD + c + 0] = l;
                split2(kv.y, h, l); Kh[r * ALD + c + 1] = h; Kl[r * ALD + c + 1] = l;
                split2(kv.z, h, l); Kh[r * ALD + c + 2] = h; Kl[r * ALD + c + 2] = l;
                split2(kv.w, h, l); Kh[r * ALD + c + 3] = h; Kl[r * ALD + c + 3] = l;
                float4 vv = *(const float4*)(vp + r * 128 + c);
                Vs[r * ALD + c + 0] = __uint_as_float(f2tf(vv.x));
                Vs[r * ALD + c + 1] = __uint_as_float(f2tf(vv.y));
                Vs[r * ALD + c + 2] = __uint_as_float(f2tf(vv.z));
                Vs[r * ALD + c + 3] = __uint_as_float(f2tf(vv.w));
            }
        }
        __syncthreads();

        // ---- S = Q K^T (tf32x2): warp computes 16 x 64 ----
        float sacc[8][4];
        #pragma unroll
        for (int nt = 0; nt < 8; nt++)
            #pragma unroll
            for (int e = 0; e < 4; e++) sacc[nt][e] = 0.f;

        #pragma unroll
        for (int ks = 0; ks < 16; ks++) {
            const int k0 = ks * 8 + qc;
            const int r = wrow + qr;
            uint32_t ah[4], al[4];
            ah[0] = __float_as_uint(Qh[r * ALD + k0]);
            ah[1] = __float_as_uint(Qh[(r + 8) * ALD + k0]);
            ah[2] = __float_as_uint(Qh[r * ALD + k0 + 4]);
            ah[3] = __float_as_uint(Qh[(r + 8) * ALD + k0 + 4]);
            al[0] = __float_as_uint(Ql[r * ALD + k0]);
            al[1] = __float_as_uint(Ql[(r + 8) * ALD + k0]);
            al[2] = __float_as_uint(Ql[r * ALD + k0 + 4]);
            al[3] = __float_as_uint(Ql[(r + 8) * ALD + k0 + 4]);
            #pragma unroll
            for (int nt = 0; nt < 8; nt++) {
                int cr = nt * 8 + qr;
                uint32_t bh0 = __float_as_uint(Kh[cr * ALD + k0]);
                uint32_t bh1 = __float_as_uint(Kh[cr * ALD + k0 + 4]);
                uint32_t bl0 = __float_as_uint(Kl[cr * ALD + k0]);
                uint32_t bl1 = __float_as_uint(Kl[cr * ALD + k0 + 4]);
                mma8(sacc[nt], ah, bh0, bh1);
                mma8(sacc[nt], ah, bl0, bl1);
                mma8(sacc[nt], al, bh0, bh1);
            }
        }

        // ---- scale + causal mask + online softmax ----
        const float scale = 0.08838834764831845f;  // 1/sqrt(128)
        const bool last = (j == qb);
        const int grow0 = qb * 64 + wrow + qr;
        float mx0 = -INFINITY, mx1 = -INFINITY;
        #pragma unroll
        for (int nt = 0; nt < 8; nt++)
            #pragma unroll
            for (int e = 0; e < 4; e++) {
                float v = sacc[nt][e] * scale;
                if (last) {
                    int col = j * 64 + nt * 8 + 2 * qc + (e & 1);
                    int grow = grow0 + ((e >> 1) << 3);
                    if (col > grow) v = -1e30f;
                }
                sacc[nt][e] = v;
                if (e < 2) mx0 = fmaxf(mx0, v); else mx1 = fmaxf(mx1, v);
            }
        mx0 = fmaxf(mx0, __shfl_xor_sync(0xffffffffu, mx0, 1));
        mx0 = fmaxf(mx0, __shfl_xor_sync(0xffffffffu, mx0, 2));
        mx1 = fmaxf(mx1, __shfl_xor_sync(0xffffffffu, mx1, 1));
        mx1 = fmaxf(mx1, __shfl_xor_sync(0xffffffffu, mx1, 2));
        float nm0 = fmaxf(m0, mx0), nm1 = fmaxf(m1, mx1);
        float f0 = __expf(m0 - nm0), f1 = __expf(m1 - nm1);
        float s0 = 0.f, s1 = 0.f;
        #pragma unroll
        for (int nt = 0; nt < 8; nt++)
            #pragma unroll
            for (int e = 0; e < 4; e++) {
                float p = __expf(sacc[nt][e] - ((e < 2) ? nm0 : nm1));
                sacc[nt][e] = p;
                if (e < 2) s0 += p; else s1 += p;
            }
        s0 += __shfl_xor_sync(0xffffffffu, s0, 1);
        s0 += __shfl_xor_sync(0xffffffffu, s0, 2);
        s1 += __shfl_xor_sync(0xffffffffu, s1, 1);
        s1 += __shfl_xor_sync(0xffffffffu, s1, 2);
        l0 = l0 * f0 + s0;
        l1 = l1 * f1 + s1;
        m0 = nm0; m1 = nm1;
        #pragma unroll
        for (int nt = 0; nt < 16; nt++)
            #pragma unroll
            for (int e = 0; e < 4; e++) oacc[nt][e] *= (e < 2) ? f0 : f1;

        // ---- stage P (split) into per-warp smem rows ----
        #pragma unroll
        for (int nt = 0; nt < 8; nt++)
            #pragma unroll
            for (int e = 0; e < 4; e++) {
                int r = wrow + qr + ((e >> 1) << 3);
                int c = nt * 8 + 2 * qc + (e & 1);
                float h, l;
                split2(sacc[nt][e], h, l);
                Ph[r * PLD + c] = h;
                Pl[r * PLD + c] = l;
            }
        __syncwarp();

        // ---- O += P V (P split x V single) ----
        #pragma unroll
        for (int ks = 0; ks < 8; ks++) {
            const int k0 = ks * 8 + qc;
            const int r = wrow + qr;
            uint32_t ah[4], al[4];
            ah[0] = __float_as_uint(Ph[r * PLD + k0]);
            ah[1] = __float_as_uint(Ph[(r + 8) * PLD + k0]);
            ah[2] = __float_as_uint(Ph[r * PLD + k0 + 4]);
            ah[3] = __float_as_uint(Ph[(r + 8) * PLD + k0 + 4]);
            al[0] = __float_as_uint(Pl[r * PLD + k0]);
            al[1] = __float_as_uint(Pl[(r + 8) * PLD + k0]);
            al[2] = __float_as_uint(Pl[r * PLD + k0 + 4]);
            al[3] = __float_as_uint(Pl[(r + 8) * PLD + k0 + 4]);
            #pragma unroll
            for (int nt = 0; nt < 16; nt++) {
                uint32_t b0 = __float_as_uint(Vs[k0 * ALD + nt * 8 + qr]);
                uint32_t b1 = __float_as_uint(Vs[(k0 + 4) * ALD + nt * 8 + qr]);
                mma8(oacc[nt], ah, b0, b1);
                mma8(oacc[nt], al, b0, b1);
            }
        }
    }

    // ---- finalize: O /= l, write to g_attn [s][b][h] ----
    const float il0 = 1.f / l0, il1 = 1.f / l1;
    const int b = hb >> 4, nh = hb & 15;
    #pragma unroll
    for (int nt = 0; nt < 16; nt++)
        #pragma unroll
        for (int e = 0; e < 4; e++) {
            int srow = qb * 64 + wrow + qr + ((e >> 1) << 3);
            int col  = nt * 8 + 2 * qc + (e & 1);
            float v = oacc[nt][e] * ((e < 2) ? il0 : il1);
            g_attn[((size_t)srow * BATCH + b) * HID + nh * HDIM + col] = v;
        }
}

// ---------------------------------------------------------------------------
// Launch
// ---------------------------------------------------------------------------
extern "C" void kernel_launch(void* const* d_in, const int* in_sizes, int n_in,
                              void* d_out, int out_size)
{
    const float* hs   = (const float*)d_in[0];  // [S,B,H]
    const float* wqkv = (const float*)d_in[1];  // [3H,H]
    const float* wout = (const float*)d_in[2];  // [H,H]
    float* out = (float*)d_out;                 // [S,B,H]

    const int gemm_smem = 4 * GBM * GLDA * sizeof(float);                 // 73728
    const int attn_smem = (5 * 64 * ALD + 2 * 64 * PLD) * sizeof(float);  // 203776

    cudaFuncSetAttribute(gemm_kernel<0>, cudaFuncAttributeMaxDynamicSharedMemorySize, gemm_smem);
    cudaFuncSetAttribute(gemm_kernel<1>, cudaFuncAttributeMaxDynamicSharedMemorySize, gemm_smem);
    cudaFuncSetAttribute(attn_kernel,    cudaFuncAttributeMaxDynamicSharedMemorySize, attn_smem);

    const int M = S_LEN * BATCH;  // 4096

    // 1) QKV projection (scatter into g_q/g_k/g_v head-major)
    gemm_kernel<0><<<dim3(3 * HID / GBN, M / GBM), 256, gemm_smem>>>(
        hs, wqkv, nullptr, M, 3 * HID, HID);

    // 2) RoPE table + apply to q,k
    rope_table_kernel<<<(S_LEN * 64) / 256, 256>>>();
    rope_apply_kernel<<<(2 * NH_B * S_LEN * 64) / 256, 256>>>();

    // 3) Causal attention -> g_attn [s][b][h]
    attn_kernel<<<dim3(S_LEN / 64, NH_B), 128, attn_smem>>>();

    // 4) Output projection -> d_out
    gemm_kernel<1><<<dim3(HID / GBN, M / GBM), 256, gemm_smem>>>(
        nullptr, wout, out, M, HID, HID);
}

// round 9
// speedup vs baseline: 2.2480x; 2.2480x over previous
#include <cuda_runtime.h>
#include <math.h>
#include <stdint.h>

// Problem constants
#define S_LEN 2048
#define BATCH 2
#define HID   2048
#define NHEAD 16
#define HDIM  128
#define NH_B  (BATCH * NHEAD)   // 32 heads total

// Scratch (device globals: no allocation allowed in kernel_launch)
__device__ float g_q[(size_t)NH_B * S_LEN * HDIM];     // [b*NH+nh][s][hd]
__device__ float g_k[(size_t)NH_B * S_LEN * HDIM];
__device__ float g_v[(size_t)NH_B * S_LEN * HDIM];
__device__ float g_attn[(size_t)S_LEN * BATCH * HID];  // [s][b][h]
__device__ float g_tab[S_LEN * 64 * 2];                // cos/sin table

// ---------------------------------------------------------------------------
// Helpers
// ---------------------------------------------------------------------------
__device__ __forceinline__ uint32_t f2tf(float x) {
    uint32_t r;
    asm("cvt.rna.tf32.f32 %0, %1;" : "=r"(r) : "f"(x));
    return r;
}

__device__ __forceinline__ void mma8(float c[4], const uint32_t a[4],
                                     uint32_t b0, uint32_t b1) {
    asm volatile(
        "mma.sync.aligned.m16n8k8.row.col.f32.tf32.tf32.f32 "
        "{%0,%1,%2,%3}, {%4,%5,%6,%7}, {%8,%9}, {%0,%1,%2,%3};"
        : "+f"(c[0]), "+f"(c[1]), "+f"(c[2]), "+f"(c[3])
        : "r"(a[0]), "r"(a[1]), "r"(a[2]), "r"(a[3]), "r"(b0), "r"(b1));
}

__device__ __forceinline__ void cpa16(uint32_t smem_b, const void* g) {
    asm volatile("cp.async.cg.shared.global [%0], [%1], 16;" :: "r"(smem_b), "l"(g));
}
__device__ __forceinline__ void cpa_commit() {
    asm volatile("cp.async.commit_group;");
}
template<int N>
__device__ __forceinline__ void cpa_wait() {
    asm volatile("cp.async.wait_group %0;" :: "n"(N));
}

__device__ __forceinline__ uint32_t smem_u32(const void* p) {
    uint32_t r;
    asm("{ .reg .u64 t; cvta.to.shared.u64 t, %1; cvt.u32.u64 %0, t; }"
        : "=r"(r) : "l"(p));
    return r;
}

// ---------------------------------------------------------------------------
// GEMM: C[M,N] = A[M,K] * W[N,K]^T, single tf32 (rna), cp.async double buffer.
// Block 256x128x32, 256 threads (8 warps as 4x2, warp tile 64x64).
// MODE 0: A = hidden_states, scatter into g_q/g_k/g_v; MODE 1: A = g_attn -> C.
// ---------------------------------------------------------------------------
#define GM 256
#define GN 128
#define GK 32
#define GLD 36                       // 32 + pad (144B row stride, 16B aligned)
#define A_FLOATS (GM * GLD)          // 9216
#define B_FLOATS (GN * GLD)          // 4608
#define STAGE_FLOATS (A_FLOATS + B_FLOATS)

__device__ __forceinline__ void gemm_stage(uint32_t sbase, int buf,
                                           const float* Ap, const float* W,
                                           int bm, int bn, int K, int kt, int t)
{
    uint32_t a0 = sbase + (uint32_t)(buf * STAGE_FLOATS) * 4u;
    uint32_t b0 = a0 + A_FLOATS * 4u;
    #pragma unroll
    for (int i = 0; i < 8; i++) {
        int ca = t + 256 * i;
        int r = ca >> 3, ch = ca & 7;
        cpa16(a0 + (uint32_t)(r * GLD + ch * 4) * 4u,
              Ap + (size_t)(bm + r) * K + kt + ch * 4);
    }
    #pragma unroll
    for (int i = 0; i < 4; i++) {
        int cb = t + 256 * i;
        int r = cb >> 3, ch = cb & 7;
        cpa16(b0 + (uint32_t)(r * GLD + ch * 4) * 4u,
              W + (size_t)(bn + r) * K + kt + ch * 4);
    }
    cpa_commit();
}

template<int MODE>
__global__ void __launch_bounds__(256)
gemm_kernel(const float* __restrict__ A_, const float* __restrict__ W,
            float* __restrict__ C, int M, int N, int K)
{
    extern __shared__ float sm[];
    const float* Ap = (MODE == 1) ? g_attn : A_;
    const uint32_t sbase = smem_u32(sm);

    const int t = threadIdx.x;
    const int warp = t >> 5, lane = t & 31;
    const int qr = lane >> 2, qc = lane & 3;
    const int bm = blockIdx.y * GM;
    const int bn = blockIdx.x * GN;
    const int wm = (warp >> 1) * 64;
    const int wn = (warp & 1) * 64;

    float acc[4][8][4];
    #pragma unroll
    for (int i = 0; i < 4; i++)
        #pragma unroll
        for (int j = 0; j < 8; j++)
            #pragma unroll
            for (int e = 0; e < 4; e++) acc[i][j][e] = 0.f;

    gemm_stage(sbase, 0, Ap, W, bm, bn, K, 0, t);

    for (int kt = 0; kt < K; kt += GK) {
        const int buf = (kt >> 5) & 1;
        if (kt + GK < K) {
            gemm_stage(sbase, buf ^ 1, Ap, W, bm, bn, K, kt + GK, t);
            cpa_wait<1>();
        } else {
            cpa_wait<0>();
        }
        __syncthreads();

        const float* As = sm + buf * STAGE_FLOATS;
        const float* Bs = As + A_FLOATS;

        #pragma unroll
        for (int ks = 0; ks < 4; ks++) {
            const int k0 = ks * 8 + qc;
            uint32_t a[4][4];
            #pragma unroll
            for (int mi = 0; mi < 4; mi++) {
                int r = wm + mi * 16 + qr;
                a[mi][0] = f2tf(As[r * GLD + k0]);
                a[mi][1] = f2tf(As[(r + 8) * GLD + k0]);
                a[mi][2] = f2tf(As[r * GLD + k0 + 4]);
                a[mi][3] = f2tf(As[(r + 8) * GLD + k0 + 4]);
            }
            #pragma unroll
            for (int ni = 0; ni < 8; ni++) {
                int cb = wn + ni * 8 + qr;
                uint32_t b0 = f2tf(Bs[cb * GLD + k0]);
                uint32_t b1 = f2tf(Bs[cb * GLD + k0 + 4]);
                #pragma unroll
                for (int mi = 0; mi < 4; mi++)
                    mma8(acc[mi][ni], a[mi], b0, b1);
            }
        }
        __syncthreads();
    }

    // Epilogue
    #pragma unroll
    for (int mi = 0; mi < 4; mi++)
        #pragma unroll
        for (int ni = 0; ni < 8; ni++)
            #pragma unroll
            for (int e = 0; e < 4; e++) {
                int row = bm + wm + mi * 16 + qr + ((e >> 1) << 3);
                int col = bn + wn + ni * 8 + 2 * qc + (e & 1);
                float v = acc[mi][ni][e];
                if (MODE == 0) {
                    int tsel = col >> 11;          // 0=q 1=k 2=v
                    int rem  = col & 2047;
                    int nh = rem >> 7, hd = rem & 127;
                    int s = row >> 1, b = row & 1;
                    float* dst = (tsel == 0) ? g_q : ((tsel == 1) ? g_k : g_v);
                    dst[((size_t)(b * NHEAD + nh) * S_LEN + s) * HDIM + hd] = v;
                } else {
                    C[(size_t)row * N + col] = v;
                }
            }
}

// ---------------------------------------------------------------------------
// RoPE
// ---------------------------------------------------------------------------
__global__ void rope_table_kernel()
{
    int idx = blockIdx.x * blockDim.x + threadIdx.x;   // 2048*64
    int s = idx >> 6, d = idx & 63;
    float e = (float)d * (1.0f / 64.0f);
    float inv = 1.0f / powf(10000.0f, e);
    float th = (float)s * inv;
    double sd, cd;
    sincos((double)th, &sd, &cd);
    g_tab[idx * 2 + 0] = (float)cd;
    g_tab[idx * 2 + 1] = (float)sd;
}

__global__ void rope_apply_kernel()
{
    int i = blockIdx.x * blockDim.x + threadIdx.x;  // 2 * 32 * 2048 * 64
    int d = i & 63;
    int s = (i >> 6) & 2047;
    int h = (i >> 17) & 31;
    int w = i >> 22;
    float c  = g_tab[((s << 6) + d) * 2 + 0];
    float sn = g_tab[((s << 6) + d) * 2 + 1];
    float* buf = w ? g_k : g_q;
    size_t base = ((size_t)h * S_LEN + s) * HDIM;
    float x0 = buf[base + d];
    float x1 = buf[base + d + 64];
    buf[base + d]      = x0 * c - x1 * sn;
    buf[base + d + 64] = x1 * c + x0 * sn;
}

// ---------------------------------------------------------------------------
// Causal flash attention: 128 q-rows per CTA, 8 warps (16 rows each),
// single-tf32 Q/K/P/V (rna), fp32 softmax stats.
// ---------------------------------------------------------------------------
#define ALD 132   // Q/K row stride (conflict-free frag loads)
#define VLD 136   // V row stride (conflict-free PV B-frag loads)
#define PLD 68

__global__ void __launch_bounds__(256, 1)
attn_kernel()
{
    extern __shared__ float sm[];
    float* Qh = sm;                       // 128 x ALD
    float* Kh = Qh + 128 * ALD;           // 64 x ALD
    float* Vs = Kh + 64 * ALD;            // 64 x VLD
    float* Ph = Vs + 64 * VLD;            // 128 x PLD

    const int t = threadIdx.x, warp = t >> 5, lane = t & 31;
    const int qr = lane >> 2, qc = lane & 3;
    const int qb = gridDim.x - 1 - blockIdx.x;   // heavy CTAs first
    const int hb = blockIdx.y;
    const size_t head_off = (size_t)hb * S_LEN * HDIM;
    const int wrow = warp * 16;

    // Load Q tile (128 x 128) as tf32
    {
        const float* qp = g_q + head_off + (size_t)qb * 128 * HDIM;
        #pragma unroll
        for (int it = 0; it < 16; it++) {
            int i = t * 4 + it * 1024;
            int r = i >> 7, c = i & 127;
            float4 v = *(const float4*)(qp + r * 128 + c);
            Qh[r * ALD + c + 0] = __uint_as_float(f2tf(v.x));
            Qh[r * ALD + c + 1] = __uint_as_float(f2tf(v.y));
            Qh[r * ALD + c + 2] = __uint_as_float(f2tf(v.z));
            Qh[r * ALD + c + 3] = __uint_as_float(f2tf(v.w));
        }
    }

    float oacc[16][4];
    #pragma unroll
    for (int i = 0; i < 16; i++)
        #pragma unroll
        for (int e = 0; e < 4; e++) oacc[i][e] = 0.f;
    float m0 = -INFINITY, m1 = -INFINITY, l0 = 0.f, l1 = 0.f;

    const int jmax = 2 * qb + 2;
    for (int j = 0; j < jmax; j++) {
        __syncthreads();
        {
            const float* kp = g_k + head_off + (size_t)j * 64 * HDIM;
            const float* vp = g_v + head_off + (size_t)j * 64 * HDIM;
            #pragma unroll
            for (int it = 0; it < 8; it++) {
                int i = t * 4 + it * 1024;
                int r = i >> 7, c = i & 127;
                float4 kv = *(const float4*)(kp + r * 128 + c);
                Kh[r * ALD + c + 0] = __uint_as_float(f2tf(kv.x));
                Kh[r * ALD + c + 1] = __uint_as_float(f2tf(kv.y));
                Kh[r * ALD + c + 2] = __uint_as_float(f2tf(kv.z));
                Kh[r * ALD + c + 3] = __uint_as_float(f2tf(kv.w));
                float4 vv = *(const float4*)(vp + r * 128 + c);
                Vs[r * VLD + c + 0] = __uint_as_float(f2tf(vv.x));
                Vs[r * VLD + c + 1] = __uint_as_float(f2tf(vv.y));
                Vs[r * VLD + c + 2] = __uint_as_float(f2tf(vv.z));
                Vs[r * VLD + c + 3] = __uint_as_float(f2tf(vv.w));
            }
        }
        __syncthreads();

        // ---- S = Q K^T (single tf32): warp computes 16 x 64 ----
        float sacc[8][4];
        #pragma unroll
        for (int nt = 0; nt < 8; nt++)
            #pragma unroll
            for (int e = 0; e < 4; e++) sacc[nt][e] = 0.f;

        #pragma unroll
        for (int ks = 0; ks < 16; ks++) {
            const int k0 = ks * 8 + qc;
            const int r = wrow + qr;
            uint32_t a[4];
            a[0] = __float_as_uint(Qh[r * ALD + k0]);
            a[1] = __float_as_uint(Qh[(r + 8) * ALD + k0]);
            a[2] = __float_as_uint(Qh[r * ALD + k0 + 4]);
            a[3] = __float_as_uint(Qh[(r + 8) * ALD + k0 + 4]);
            #pragma unroll
            for (int nt = 0; nt < 8; nt++) {
                int cr = nt * 8 + qr;
                uint32_t b0 = __float_as_uint(Kh[cr * ALD + k0]);
                uint32_t b1 = __float_as_uint(Kh[cr * ALD + k0 + 4]);
                mma8(sacc[nt], a, b0, b1);
            }
        }

        // ---- scale + causal mask + online softmax ----
        const float scale = 0.08838834764831845f;  // 1/sqrt(128)
        const bool maskt = (j >= 2 * qb);
        const int grow0 = qb * 128 + wrow + qr;
        float mx0 = -INFINITY, mx1 = -INFINITY;
        #pragma unroll
        for (int nt = 0; nt < 8; nt++)
            #pragma unroll
            for (int e = 0; e < 4; e++) {
                float v = sacc[nt][e] * scale;
                if (maskt) {
                    int col = j * 64 + nt * 8 + 2 * qc + (e & 1);
                    int grow = grow0 + ((e >> 1) << 3);
                    if (col > grow) v = -1e30f;
                }
                sacc[nt][e] = v;
                if (e < 2) mx0 = fmaxf(mx0, v); else mx1 = fmaxf(mx1, v);
            }
        mx0 = fmaxf(mx0, __shfl_xor_sync(0xffffffffu, mx0, 1));
        mx0 = fmaxf(mx0, __shfl_xor_sync(0xffffffffu, mx0, 2));
        mx1 = fmaxf(mx1, __shfl_xor_sync(0xffffffffu, mx1, 1));
        mx1 = fmaxf(mx1, __shfl_xor_sync(0xffffffffu, mx1, 2));
        float nm0 = fmaxf(m0, mx0), nm1 = fmaxf(m1, mx1);
        float f0 = __expf(m0 - nm0), f1 = __expf(m1 - nm1);
        float s0 = 0.f, s1 = 0.f;
        #pragma unroll
        for (int nt = 0; nt < 8; nt++)
            #pragma unroll
            for (int e = 0; e < 4; e++) {
                float p = __expf(sacc[nt][e] - ((e < 2) ? nm0 : nm1));
                sacc[nt][e] = p;
                if (e < 2) s0 += p; else s1 += p;
            }
        s0 += __shfl_xor_sync(0xffffffffu, s0, 1);
        s0 += __shfl_xor_sync(0xffffffffu, s0, 2);
        s1 += __shfl_xor_sync(0xffffffffu, s1, 1);
        s1 += __shfl_xor_sync(0xffffffffu, s1, 2);
        l0 = l0 * f0 + s0;
        l1 = l1 * f1 + s1;
        m0 = nm0; m1 = nm1;
        #pragma unroll
        for (int nt = 0; nt < 16; nt++)
            #pragma unroll
            for (int e = 0; e < 4; e++) oacc[nt][e] *= (e < 2) ? f0 : f1;

        // ---- stage P (single tf32) into per-warp smem rows ----
        #pragma unroll
        for (int nt = 0; nt < 8; nt++)
            #pragma unroll
            for (int e = 0; e < 4; e++) {
                int r = wrow + qr + ((e >> 1) << 3);
                int c = nt * 8 + 2 * qc + (e & 1);
                Ph[r * PLD + c] = __uint_as_float(f2tf(sacc[nt][e]));
            }
        __syncwarp();

        // ---- O += P V ----
        #pragma unroll
        for (int ks = 0; ks < 8; ks++) {
            const int k0 = ks * 8 + qc;
            const int r = wrow + qr;
            uint32_t a[4];
            a[0] = __float_as_uint(Ph[r * PLD + k0]);
            a[1] = __float_as_uint(Ph[(r + 8) * PLD + k0]);
            a[2] = __float_as_uint(Ph[r * PLD + k0 + 4]);
            a[3] = __float_as_uint(Ph[(r + 8) * PLD + k0 + 4]);
            #pragma unroll
            for (int nt = 0; nt < 16; nt++) {
                uint32_t b0 = __float_as_uint(Vs[k0 * VLD + nt * 8 + qr]);
                uint32_t b1 = __float_as_uint(Vs[(k0 + 4) * VLD + nt * 8 + qr]);
                mma8(oacc[nt], a, b0, b1);
            }
        }
    }

    // ---- finalize: O /= l, write to g_attn [s][b][h] ----
    const float il0 = 1.f / l0, il1 = 1.f / l1;
    const int b = hb >> 4, nh = hb & 15;
    #pragma unroll
    for (int nt = 0; nt < 16; nt++)
        #pragma unroll
        for (int e = 0; e < 4; e++) {
            int srow = qb * 128 + wrow + qr + ((e >> 1) << 3);
            int col  = nt * 8 + 2 * qc + (e & 1);
            float v = oacc[nt][e] * ((e < 2) ? il0 : il1);
            g_attn[((size_t)srow * BATCH + b) * HID + nh * HDIM + col] = v;
        }
}

// ---------------------------------------------------------------------------
// Launch
// ---------------------------------------------------------------------------
extern "C" void kernel_launch(void* const* d_in, const int* in_sizes, int n_in,
                              void* d_out, int out_size)
{
    const float* hs   = (const float*)d_in[0];  // [S,B,H]
    const float* wqkv = (const float*)d_in[1];  // [3H,H]
    const float* wout = (const float*)d_in[2];  // [H,H]
    float* out = (float*)d_out;                 // [S,B,H]

    const int gemm_smem = 2 * STAGE_FLOATS * sizeof(float);               // 110592
    const int attn_smem = (128 * ALD + 64 * ALD + 64 * VLD + 128 * PLD) * sizeof(float); // 171008

    cudaFuncSetAttribute(gemm_kernel<0>, cudaFuncAttributeMaxDynamicSharedMemorySize, gemm_smem);
    cudaFuncSetAttribute(gemm_kernel<1>, cudaFuncAttributeMaxDynamicSharedMemorySize, gemm_smem);
    cudaFuncSetAttribute(attn_kernel,    cudaFuncAttributeMaxDynamicSharedMemorySize, attn_smem);

    const int M = S_LEN * BATCH;  // 4096

    // 1) QKV projection (scatter into g_q/g_k/g_v head-major)
    gemm_kernel<0><<<dim3(3 * HID / GN, M / GM), 256, gemm_smem>>>(
        hs, wqkv, nullptr, M, 3 * HID, HID);

    // 2) RoPE table + apply to q,k
    rope_table_kernel<<<(S_LEN * 64) / 256, 256>>>();
    rope_apply_kernel<<<(2 * NH_B * S_LEN * 64) / 256, 256>>>();

    // 3) Causal attention -> g_attn [s][b][h]
    attn_kernel<<<dim3(S_LEN / 128, NH_B), 256, attn_smem>>>();

    // 4) Output projection -> d_out
    gemm_kernel<1><<<dim3(HID / GN, M / GM), 256, gemm_smem>>>(
        nullptr, wout, out, M, HID, HID);
}

// round 10
// speedup vs baseline: 2.2524x; 1.0020x over previous
#include <cuda_runtime.h>
#include <math.h>
#include <stdint.h>

// Problem constants
#define S_LEN 2048
#define BATCH 2
#define HID   2048
#define NHEAD 16
#define HDIM  128
#define NH_B  (BATCH * NHEAD)   // 32 heads total

// Scratch (device globals: no allocation allowed in kernel_launch)
__device__ float g_q[(size_t)NH_B * S_LEN * HDIM];     // [b*NH+nh][s][hd]
__device__ float g_k[(size_t)NH_B * S_LEN * HDIM];
__device__ float g_v[(size_t)NH_B * S_LEN * HDIM];
__device__ float g_attn[(size_t)S_LEN * BATCH * HID];  // [s][b][h]
__device__ float g_tab[S_LEN * 64 * 2];                // cos/sin table

// ---------------------------------------------------------------------------
// Helpers
// ---------------------------------------------------------------------------
__device__ __forceinline__ uint32_t f2tf(float x) {
    uint32_t r;
    asm("cvt.rna.tf32.f32 %0, %1;" : "=r"(r) : "f"(x));
    return r;
}

__device__ __forceinline__ void mma8(float c[4], const uint32_t a[4],
                                     uint32_t b0, uint32_t b1) {
    asm volatile(
        "mma.sync.aligned.m16n8k8.row.col.f32.tf32.tf32.f32 "
        "{%0,%1,%2,%3}, {%4,%5,%6,%7}, {%8,%9}, {%0,%1,%2,%3};"
        : "+f"(c[0]), "+f"(c[1]), "+f"(c[2]), "+f"(c[3])
        : "r"(a[0]), "r"(a[1]), "r"(a[2]), "r"(a[3]), "r"(b0), "r"(b1));
}

__device__ __forceinline__ void cpa16(uint32_t smem_b, const void* g) {
    asm volatile("cp.async.cg.shared.global [%0], [%1], 16;" :: "r"(smem_b), "l"(g));
}
__device__ __forceinline__ void cpa_commit() {
    asm volatile("cp.async.commit_group;");
}
template<int N>
__device__ __forceinline__ void cpa_wait() {
    asm volatile("cp.async.wait_group %0;" :: "n"(N));
}

__device__ __forceinline__ uint32_t smem_u32(const void* p) {
    uint32_t r;
    asm("{ .reg .u64 t; cvta.to.shared.u64 t, %1; cvt.u32.u64 %0, t; }"
        : "=r"(r) : "l"(p));
    return r;
}

// ---------------------------------------------------------------------------
// GEMM: C[M,N] = A[M,K] * W[N,K]^T, single tf32 (rna), cp.async double buffer.
// Block 256x128x32, 256 threads (8 warps as 4x2, warp tile 64x64).
// MODE 0: A = hidden_states, scatter into g_q/g_k/g_v; MODE 1: A = g_attn -> C.
// ---------------------------------------------------------------------------
#define GM 256
#define GN 128
#define GK 32
#define GLD 36                       // 32 + pad (144B row stride, 16B aligned)
#define A_FLOATS (GM * GLD)          // 9216
#define B_FLOATS (GN * GLD)          // 4608
#define STAGE_FLOATS (A_FLOATS + B_FLOATS)

__device__ __forceinline__ void gemm_stage(uint32_t sbase, int buf,
                                           const float* Ap, const float* W,
                                           int bm, int bn, int K, int kt, int t)
{
    uint32_t a0 = sbase + (uint32_t)(buf * STAGE_FLOATS) * 4u;
    uint32_t b0 = a0 + A_FLOATS * 4u;
    #pragma unroll
    for (int i = 0; i < 8; i++) {
        int ca = t + 256 * i;
        int r = ca >> 3, ch = ca & 7;
        cpa16(a0 + (uint32_t)(r * GLD + ch * 4) * 4u,
              Ap + (size_t)(bm + r) * K + kt + ch * 4);
    }
    #pragma unroll
    for (int i = 0; i < 4; i++) {
        int cb = t + 256 * i;
        int r = cb >> 3, ch = cb & 7;
        cpa16(b0 + (uint32_t)(r * GLD + ch * 4) * 4u,
              W + (size_t)(bn + r) * K + kt + ch * 4);
    }
    cpa_commit();
}

template<int MODE>
__global__ void __launch_bounds__(256)
gemm_kernel(const float* __restrict__ A_, const float* __restrict__ W,
            float* __restrict__ C, int M, int N, int K)
{
    extern __shared__ float sm[];
    const float* Ap = (MODE == 1) ? g_attn : A_;
    const uint32_t sbase = smem_u32(sm);

    const int t = threadIdx.x;
    const int warp = t >> 5, lane = t & 31;
    const int qr = lane >> 2, qc = lane & 3;
    const int bm = blockIdx.y * GM;
    const int bn = blockIdx.x * GN;
    const int wm = (warp >> 1) * 64;
    const int wn = (warp & 1) * 64;

    float acc[4][8][4];
    #pragma unroll
    for (int i = 0; i < 4; i++)
        #pragma unroll
        for (int j = 0; j < 8; j++)
            #pragma unroll
            for (int e = 0; e < 4; e++) acc[i][j][e] = 0.f;

    gemm_stage(sbase, 0, Ap, W, bm, bn, K, 0, t);

    for (int kt = 0; kt < K; kt += GK) {
        const int buf = (kt >> 5) & 1;
        if (kt + GK < K) {
            gemm_stage(sbase, buf ^ 1, Ap, W, bm, bn, K, kt + GK, t);
            cpa_wait<1>();
        } else {
            cpa_wait<0>();
        }
        __syncthreads();

        const float* As = sm + buf * STAGE_FLOATS;
        const float* Bs = As + A_FLOATS;

        #pragma unroll
        for (int ks = 0; ks < 4; ks++) {
            const int k0 = ks * 8 + qc;
            uint32_t a[4][4];
            #pragma unroll
            for (int mi = 0; mi < 4; mi++) {
                int r = wm + mi * 16 + qr;
                a[mi][0] = f2tf(As[r * GLD + k0]);
                a[mi][1] = f2tf(As[(r + 8) * GLD + k0]);
                a[mi][2] = f2tf(As[r * GLD + k0 + 4]);
                a[mi][3] = f2tf(As[(r + 8) * GLD + k0 + 4]);
            }
            #pragma unroll
            for (int ni = 0; ni < 8; ni++) {
                int cb = wn + ni * 8 + qr;
                uint32_t b0 = f2tf(Bs[cb * GLD + k0]);
                uint32_t b1 = f2tf(Bs[cb * GLD + k0 + 4]);
                #pragma unroll
                for (int mi = 0; mi < 4; mi++)
                    mma8(acc[mi][ni], a[mi], b0, b1);
            }
        }
        __syncthreads();
    }

    // Epilogue
    #pragma unroll
    for (int mi = 0; mi < 4; mi++)
        #pragma unroll
        for (int ni = 0; ni < 8; ni++)
            #pragma unroll
            for (int e = 0; e < 4; e++) {
                int row = bm + wm + mi * 16 + qr + ((e >> 1) << 3);
                int col = bn + wn + ni * 8 + 2 * qc + (e & 1);
                float v = acc[mi][ni][e];
                if (MODE == 0) {
                    int tsel = col >> 11;          // 0=q 1=k 2=v
                    int rem  = col & 2047;
                    int nh = rem >> 7, hd = rem & 127;
                    int s = row >> 1, b = row & 1;
                    float* dst = (tsel == 0) ? g_q : ((tsel == 1) ? g_k : g_v);
                    dst[((size_t)(b * NHEAD + nh) * S_LEN + s) * HDIM + hd] = v;
                } else {
                    C[(size_t)row * N + col] = v;
                }
            }
}

// ---------------------------------------------------------------------------
// RoPE
// ---------------------------------------------------------------------------
__global__ void rope_table_kernel()
{
    int idx = blockIdx.x * blockDim.x + threadIdx.x;   // 2048*64
    int s = idx >> 6, d = idx & 63;
    float e = (float)d * (1.0f / 64.0f);
    float inv = 1.0f / powf(10000.0f, e);
    float th = (float)s * inv;
    double sd, cd;
    sincos((double)th, &sd, &cd);
    g_tab[idx * 2 + 0] = (float)cd;
    g_tab[idx * 2 + 1] = (float)sd;
}

__global__ void rope_apply_kernel()
{
    int i = blockIdx.x * blockDim.x + threadIdx.x;  // 2 * 32 * 2048 * 64
    int d = i & 63;
    int s = (i >> 6) & 2047;
    int h = (i >> 17) & 31;
    int w = i >> 22;
    float c  = g_tab[((s << 6) + d) * 2 + 0];
    float sn = g_tab[((s << 6) + d) * 2 + 1];
    float* buf = w ? g_k : g_q;
    size_t base = ((size_t)h * S_LEN + s) * HDIM;
    float x0 = buf[base + d];
    float x1 = buf[base + d + 64];
    buf[base + d]      = x0 * c - x1 * sn;
    buf[base + d + 64] = x1 * c + x0 * sn;
}

// ---------------------------------------------------------------------------
// Causal flash attention: 128 q-rows per CTA, 8 warps (16 rows each),
// single-tf32 Q/K/P/V (rna), fp32 softmax stats.
// ---------------------------------------------------------------------------
#define ALD 132   // Q/K row stride (conflict-free frag loads)
#define VLD 136   // V row stride (conflict-free PV B-frag loads)
#define PLD 68

__global__ void __launch_bounds__(256, 1)
attn_kernel()
{
    extern __shared__ float sm[];
    float* Qh = sm;                       // 128 x ALD
    float* Kh = Qh + 128 * ALD;           // 64 x ALD
    float* Vs = Kh + 64 * ALD;            // 64 x VLD
    float* Ph = Vs + 64 * VLD;            // 128 x PLD

    const int t = threadIdx.x, warp = t >> 5, lane = t & 31;
    const int qr = lane >> 2, qc = lane & 3;
    const int qb = gridDim.x - 1 - blockIdx.x;   // heavy CTAs first
    const int hb = blockIdx.y;
    const size_t head_off = (size_t)hb * S_LEN * HDIM;
    const int wrow = warp * 16;

    // Load Q tile (128 x 128) as tf32
    {
        const float* qp = g_q + head_off + (size_t)qb * 128 * HDIM;
        #pragma unroll
        for (int it = 0; it < 16; it++) {
            int i = t * 4 + it * 1024;
            int r = i >> 7, c = i & 127;
            float4 v = *(const float4*)(qp + r * 128 + c);
            Qh[r * ALD + c + 0] = __uint_as_float(f2tf(v.x));
            Qh[r * ALD + c + 1] = __uint_as_float(f2tf(v.y));
            Qh[r * ALD + c + 2] = __uint_as_float(f2tf(v.z));
            Qh[r * ALD + c + 3] = __uint_as_float(f2tf(v.w));
        }
    }

    float oacc[16][4];
    #pragma unroll
    for (int i = 0; i < 16; i++)
        #pragma unroll
        for (int e = 0; e < 4; e++) oacc[i][e] = 0.f;
    float m0 = -INFINITY, m1 = -INFINITY, l0 = 0.f, l1 = 0.f;

    const int jmax = 2 * qb + 2;
    for (int j = 0; j < jmax; j++) {
        __syncthreads();
        {
            const float* kp = g_k + head_off + (size_t)j * 64 * HDIM;
            const float* vp = g_v + head_off + (size_t)j * 64 * HDIM;
            #pragma unroll
            for (int it = 0; it < 8; it++) {
                int i = t * 4 + it * 1024;
                int r = i >> 7, c = i & 127;
                float4 kv = *(const float4*)(kp + r * 128 + c);
                Kh[r * ALD + c + 0] = __uint_as_float(f2tf(kv.x));
                Kh[r * ALD + c + 1] = __uint_as_float(f2tf(kv.y));
                Kh[r * ALD + c + 2] = __uint_as_float(f2tf(kv.z));
                Kh[r * ALD + c + 3] = __uint_as_float(f2tf(kv.w));
                float4 vv = *(const float4*)(vp + r * 128 + c);
                Vs[r * VLD + c + 0] = __uint_as_float(f2tf(vv.x));
                Vs[r * VLD + c + 1] = __uint_as_float(f2tf(vv.y));
                Vs[r * VLD + c + 2] = __uint_as_float(f2tf(vv.z));
                Vs[r * VLD + c + 3] = __uint_as_float(f2tf(vv.w));
            }
        }
        __syncthreads();

        // ---- S = Q K^T (single tf32): warp computes 16 x 64 ----
        float sacc[8][4];
        #pragma unroll
        for (int nt = 0; nt < 8; nt++)
            #pragma unroll
            for (int e = 0; e < 4; e++) sacc[nt][e] = 0.f;

        #pragma unroll
        for (int ks = 0; ks < 16; ks++) {
            const int k0 = ks * 8 + qc;
            const int r = wrow + qr;
            uint32_t a[4];
            a[0] = __float_as_uint(Qh[r * ALD + k0]);
            a[1] = __float_as_uint(Qh[(r + 8) * ALD + k0]);
            a[2] = __float_as_uint(Qh[r * ALD + k0 + 4]);
            a[3] = __float_as_uint(Qh[(r + 8) * ALD + k0 + 4]);
            #pragma unroll
            for (int nt = 0; nt < 8; nt++) {
                int cr = nt * 8 + qr;
                uint32_t b0 = __float_as_uint(Kh[cr * ALD + k0]);
                uint32_t b1 = __float_as_uint(Kh[cr * ALD + k0 + 4]);
                mma8(sacc[nt], a, b0, b1);
            }
        }

        // ---- scale + causal mask + online softmax ----
        const float scale = 0.08838834764831845f;  // 1/sqrt(128)
        const bool maskt = (j >= 2 * qb);
        const int grow0 = qb * 128 + wrow + qr;
        float mx0 = -INFINITY, mx1 = -INFINITY;
        #pragma unroll
        for (int nt = 0; nt < 8; nt++)
            #pragma unroll
            for (int e = 0; e < 4; e++) {
                float v = sacc[nt][e] * scale;
                if (maskt) {
                    int col = j * 64 + nt * 8 + 2 * qc + (e & 1);
                    int grow = grow0 + ((e >> 1) << 3);
                    if (col > grow) v = -1e30f;
                }
                sacc[nt][e] = v;
                if (e < 2) mx0 = fmaxf(mx0, v); else mx1 = fmaxf(mx1, v);
            }
        mx0 = fmaxf(mx0, __shfl_xor_sync(0xffffffffu, mx0, 1));
        mx0 = fmaxf(mx0, __shfl_xor_sync(0xffffffffu, mx0, 2));
        mx1 = fmaxf(mx1, __shfl_xor_sync(0xffffffffu, mx1, 1));
        mx1 = fmaxf(mx1, __shfl_xor_sync(0xffffffffu, mx1, 2));
        float nm0 = fmaxf(m0, mx0), nm1 = fmaxf(m1, mx1);
        float f0 = __expf(m0 - nm0), f1 = __expf(m1 - nm1);
        float s0 = 0.f, s1 = 0.f;
        #pragma unroll
        for (int nt = 0; nt < 8; nt++)
            #pragma unroll
            for (int e = 0; e < 4; e++) {
                float p = __expf(sacc[nt][e] - ((e < 2) ? nm0 : nm1));
                sacc[nt][e] = p;
                if (e < 2) s0 += p; else s1 += p;
            }
        s0 += __shfl_xor_sync(0xffffffffu, s0, 1);
        s0 += __shfl_xor_sync(0xffffffffu, s0, 2);
        s1 += __shfl_xor_sync(0xffffffffu, s1, 1);
        s1 += __shfl_xor_sync(0xffffffffu, s1, 2);
        l0 = l0 * f0 + s0;
        l1 = l1 * f1 + s1;
        m0 = nm0; m1 = nm1;
        #pragma unroll
        for (int nt = 0; nt < 16; nt++)
            #pragma unroll
            for (int e = 0; e < 4; e++) oacc[nt][e] *= (e < 2) ? f0 : f1;

        // ---- stage P (single tf32) into per-warp smem rows ----
        #pragma unroll
        for (int nt = 0; nt < 8; nt++)
            #pragma unroll
            for (int e = 0; e < 4; e++) {
                int r = wrow + qr + ((e >> 1) << 3);
                int c = nt * 8 + 2 * qc + (e & 1);
                Ph[r * PLD + c] = __uint_as_float(f2tf(sacc[nt][e]));
            }
        __syncwarp();

        // ---- O += P V ----
        #pragma unroll
        for (int ks = 0; ks < 8; ks++) {
            const int k0 = ks * 8 + qc;
            const int r = wrow + qr;
            uint32_t a[4];
            a[0] = __float_as_uint(Ph[r * PLD + k0]);
            a[1] = __float_as_uint(Ph[(r + 8) * PLD + k0]);
            a[2] = __float_as_uint(Ph[r * PLD + k0 + 4]);
            a[3] = __float_as_uint(Ph[(r + 8) * PLD + k0 + 4]);
            #pragma unroll
            for (int nt = 0; nt < 16; nt++) {
                uint32_t b0 = __float_as_uint(Vs[k0 * VLD + nt * 8 + qr]);
                uint32_t b1 = __float_as_uint(Vs[(k0 + 4) * VLD + nt * 8 + qr]);
                mma8(oacc[nt], a, b0, b1);
            }
        }
    }

    // ---- finalize: O /= l, write to g_attn [s][b][h] ----
    const float il0 = 1.f / l0, il1 = 1.f / l1;
    const int b = hb >> 4, nh = hb & 15;
    #pragma unroll
    for (int nt = 0; nt < 16; nt++)
        #pragma unroll
        for (int e = 0; e < 4; e++) {
            int srow = qb * 128 + wrow + qr + ((e >> 1) << 3);
            int col  = nt * 8 + 2 * qc + (e & 1);
            float v = oacc[nt][e] * ((e < 2) ? il0 : il1);
            g_attn[((size_t)srow * BATCH + b) * HID + nh * HDIM + col] = v;
        }
}

// ---------------------------------------------------------------------------
// Launch
// ---------------------------------------------------------------------------
extern "C" void kernel_launch(void* const* d_in, const int* in_sizes, int n_in,
                              void* d_out, int out_size)
{
    const float* hs   = (const float*)d_in[0];  // [S,B,H]
    const float* wqkv = (const float*)d_in[1];  // [3H,H]
    const float* wout = (const float*)d_in[2];  // [H,H]
    float* out = (float*)d_out;                 // [S,B,H]

    const int gemm_smem = 2 * STAGE_FLOATS * sizeof(float);               // 110592
    const int attn_smem = (128 * ALD + 64 * ALD + 64 * VLD + 128 * PLD) * sizeof(float); // 171008

    cudaFuncSetAttribute(gemm_kernel<0>, cudaFuncAttributeMaxDynamicSharedMemorySize, gemm_smem);
    cudaFuncSetAttribute(gemm_kernel<1>, cudaFuncAttributeMaxDynamicSharedMemorySize, gemm_smem);
    cudaFuncSetAttribute(attn_kernel,    cudaFuncAttributeMaxDynamicSharedMemorySize, attn_smem);

    const int M = S_LEN * BATCH;  // 4096

    // 1) QKV projection (scatter into g_q/g_k/g_v head-major)
    gemm_kernel<0><<<dim3(3 * HID / GN, M / GM), 256, gemm_smem>>>(
        hs, wqkv, nullptr, M, 3 * HID, HID);

    // 2) RoPE table + apply to q,k
    rope_table_kernel<<<(S_LEN * 64) / 256, 256>>>();
    rope_apply_kernel<<<(2 * NH_B * S_LEN * 64) / 256, 256>>>();

    // 3) Causal attention -> g_attn [s][b][h]
    attn_kernel<<<dim3(S_LEN / 128, NH_B), 256, attn_smem>>>();

    // 4) Output projection -> d_out
    gemm_kernel<1><<<dim3(HID / GN, M / GM), 256, gemm_smem>>>(
        nullptr, wout, out, M, HID, HID);
}